// round 4
// baseline (speedup 1.0000x reference)
#include <cuda_runtime.h>
#include <math.h>

#define M_ANCH   589824
#define NCLS     80
#define K_TOP    1000
#define CAND_CAP 4096
#define NBINS    2048
#define GRID     144
#define NTHR     1024
#define ROWS_PER_BLK 4096          /* M_ANCH / GRID */
#define NBAR_FINAL 8
#define IMG_INV  (1.0f/2048.0f)
#define SCALE_CLAMP 4.1351665567423560f   /* log(1000/16) */
#define SMEM_BYTES 132096          /* >= 1000*32*4 + 1000*4 */

// ---------------- scratch (device globals; no allocations allowed) ----------
__device__ unsigned            g_key[M_ANCH];
__device__ unsigned            g_hist1[NBINS];
__device__ unsigned            g_hist2[NBINS];
__device__ unsigned            g_B1;
__device__ unsigned            g_cntAbove1;
__device__ unsigned            g_thresh;
__device__ unsigned            g_candCount;
__device__ unsigned long long  g_cand[CAND_CAP];
__device__ int                 g_selIdx[K_TOP];
__device__ float4              g_boxes[K_TOP];
__device__ int                 g_labels[K_TOP];
__device__ int                 g_valid[K_TOP];
__device__ unsigned            g_mask[K_TOP * 32];
__device__ unsigned            g_barrier;   // starts 0; reset to 0 every run

// ---------------- helpers ---------------------------------------------------
__device__ __forceinline__ unsigned f2ord(float f) {
    unsigned u = __float_as_uint(f);
    return (u & 0x80000000u) ? ~u : (u | 0x80000000u);
}
// Sigmoid matching XLA lowering of lax.logistic on GPU (bit-stable vs ref).
__device__ __forceinline__ float ref_sigmoid(float x) {
    float e = expf(-x);
    return __fdiv_rn(1.0f, __fadd_rn(1.0f, e));
}

// software grid barrier: monotone counter; k = 1..NBAR_FINAL.
// Final barrier resets counter to 0 (last arriver), so every run starts clean.
__device__ __forceinline__ void gridsync(int k) {
    __syncthreads();
    if (threadIdx.x == 0) {
        __threadfence();
        unsigned target = (unsigned)k * GRID;
        unsigned old = atomicAdd(&g_barrier, 1u);
        volatile unsigned* p = &g_barrier;
        if (k == NBAR_FINAL) {
            if (old + 1u == target) {
                atomicExch(&g_barrier, 0u);
            } else {
                while (true) { unsigned v = *p; if (v == 0u || v >= target) break; }
            }
        } else {
            while (*p < target) { }
        }
        __threadfence();
    }
    __syncthreads();
}

// suffix-scan of a 2048-bin hist in smem; returns via pointers (block0 only)
__device__ __forceinline__ void suffix_find(const unsigned* __restrict__ gh,
                                            unsigned base_extra,
                                            unsigned* sh, int* sbest,
                                            unsigned* out_bin, unsigned* out_above) {
    int t = threadIdx.x;
    sh[t] = gh[t]; sh[t + 1024] = gh[t + 1024];
    if (t == 0) *sbest = -1;
    __syncthreads();
    for (int off = 1; off < NBINS; off <<= 1) {
        unsigned a = (t + off < NBINS) ? sh[t + off] : 0u;
        unsigned b = (t + 1024 + off < NBINS) ? sh[t + 1024 + off] : 0u;
        __syncthreads();
        sh[t] += a; sh[t + 1024] += b;
        __syncthreads();
    }
    if (base_extra + sh[t] >= K_TOP)        atomicMax(sbest, t);
    if (base_extra + sh[t + 1024] >= K_TOP) atomicMax(sbest, t + 1024);
    __syncthreads();
    if (t == 0) {
        int bb = *sbest;
        *out_bin = (unsigned)bb;
        if (out_above)
            *out_above = (bb < NBINS - 1) ? sh[bb + 1] : 0u;
    }
    __syncthreads();
}

// ---------------- the mega kernel -------------------------------------------
__global__ void __launch_bounds__(NTHR, 1)
k_mega(const float* __restrict__ cls, const float* __restrict__ reg,
       const float* __restrict__ anc, float* __restrict__ out) {
    extern __shared__ unsigned smem_u[];
    const int t = threadIdx.x;
    const int b = blockIdx.x;

    // ===== phase 1: rowmax + sigmoid key + hist1 =============================
    {
        unsigned* sh = smem_u;
        sh[t] = 0u; sh[t + 1024] = 0u;
        __syncthreads();
        const int base = b * ROWS_PER_BLK;
#pragma unroll
        for (int r = 0; r < 4; r++) {
            int row = base + r * 1024 + t;
            const float4* p = (const float4*)(cls + (size_t)row * NCLS);
            float m = __int_as_float(0xff800000);
#pragma unroll
            for (int q = 0; q < NCLS / 4; q++) {
                float4 v = p[q];
                m = fmaxf(m, fmaxf(fmaxf(v.x, v.y), fmaxf(v.z, v.w)));
            }
            unsigned key = f2ord(ref_sigmoid(m));
            g_key[row] = key;
            atomicAdd(&sh[key >> 21], 1u);
        }
        __syncthreads();
        unsigned c0 = sh[t], c1 = sh[t + 1024];
        if (c0) atomicAdd(&g_hist1[t], c0);
        if (c1) atomicAdd(&g_hist1[t + 1024], c1);
    }
    gridsync(1);

    // ===== phase 2: block0 finds coarse bin B1 ===============================
    if (b == 0) {
        suffix_find(g_hist1, 0u, smem_u, (int*)&smem_u[NBINS],
                    &g_B1, &g_cntAbove1);
    }
    gridsync(2);

    // ===== phase 3: refined histogram within bin B1; blk GRID-1 zeroes hist1 =
    {
        unsigned* sh = smem_u;
        sh[t] = 0u; sh[t + 1024] = 0u;
        __syncthreads();
        unsigned B1 = g_B1;
        const uint4* kp = (const uint4*)g_key;
        int base4 = b * (ROWS_PER_BLK / 4);
        for (int e = 0; e < 1; e++) {
            uint4 k4 = kp[base4 + t];
            if ((k4.x >> 21) == B1) atomicAdd(&sh[(k4.x >> 10) & 2047u], 1u);
            if ((k4.y >> 21) == B1) atomicAdd(&sh[(k4.y >> 10) & 2047u], 1u);
            if ((k4.z >> 21) == B1) atomicAdd(&sh[(k4.z >> 10) & 2047u], 1u);
            if ((k4.w >> 21) == B1) atomicAdd(&sh[(k4.w >> 10) & 2047u], 1u);
        }
        __syncthreads();
        unsigned c0 = sh[t], c1 = sh[t + 1024];
        if (c0) atomicAdd(&g_hist2[t], c0);
        if (c1) atomicAdd(&g_hist2[t + 1024], c1);
        if (b == GRID - 1) { g_hist1[t] = 0u; g_hist1[t + 1024] = 0u; }
    }
    gridsync(3);

    // ===== phase 4: block0 finds refined threshold ===========================
    if (b == 0) {
        __shared__ unsigned bin2;
        suffix_find(g_hist2, g_cntAbove1, smem_u, (int*)&smem_u[NBINS],
                    &bin2, 0);
        if (t == 0) g_thresh = (g_B1 << 21) | (bin2 << 10);
    }
    gridsync(4);

    // ===== phase 5: compact candidates >= thresh =============================
    {
        unsigned thr = g_thresh;
        const uint4* kp = (const uint4*)g_key;
        int i4 = b * (ROWS_PER_BLK / 4) + t;
        uint4 k4 = kp[i4];
        int i0 = i4 * 4;
        if (k4.x >= thr) {
            unsigned pos = atomicAdd(&g_candCount, 1u);
            if (pos < CAND_CAP)
                g_cand[pos] = ((unsigned long long)k4.x << 32) | (unsigned)(~(i0 + 0));
        }
        if (k4.y >= thr) {
            unsigned pos = atomicAdd(&g_candCount, 1u);
            if (pos < CAND_CAP)
                g_cand[pos] = ((unsigned long long)k4.y << 32) | (unsigned)(~(i0 + 1));
        }
        if (k4.z >= thr) {
            unsigned pos = atomicAdd(&g_candCount, 1u);
            if (pos < CAND_CAP)
                g_cand[pos] = ((unsigned long long)k4.z << 32) | (unsigned)(~(i0 + 2));
        }
        if (k4.w >= thr) {
            unsigned pos = atomicAdd(&g_candCount, 1u);
            if (pos < CAND_CAP)
                g_cand[pos] = ((unsigned long long)k4.w << 32) | (unsigned)(~(i0 + 3));
        }
    }
    gridsync(5);

    // ===== phase 6: O(n^2) rank -> selIdx; blk GRID-2 zeroes hist2 ==========
    {
        unsigned cnt = min(g_candCount, (unsigned)CAND_CAP);
        if ((unsigned)(b * NTHR) < cnt) {
            unsigned long long* s = (unsigned long long*)smem_u;
            for (unsigned j = t; j < cnt; j += NTHR) s[j] = g_cand[j];
            __syncthreads();
            unsigned id = b * NTHR + t;
            if (id < cnt) {
                unsigned long long my = s[id];
                unsigned rank = 0, j = 0;
                for (; j + 4 <= cnt; j += 4) {
                    rank += (s[j]     > my);
                    rank += (s[j + 1] > my);
                    rank += (s[j + 2] > my);
                    rank += (s[j + 3] > my);
                }
                for (; j < cnt; j++) rank += (s[j] > my);
                if (rank < K_TOP)
                    g_selIdx[rank] = (int)(~(unsigned)(my & 0xFFFFFFFFULL));
            }
        }
        if (b == GRID - 2) { g_hist2[t] = 0u; g_hist2[t + 1024] = 0u; }
    }
    gridsync(6);

    // ===== phase 7: block0 decodes the 1000 winners ==========================
    if (b == 0 && t < K_TOP) {
        int i = g_selIdx[t];
        const float4* row = (const float4*)(cls + (size_t)i * NCLS);
        float best = -1.0f; int bl = 0;
#pragma unroll
        for (int q = 0; q < NCLS / 4; q++) {
            float4 v = row[q];
            float s0 = ref_sigmoid(v.x), s1 = ref_sigmoid(v.y);
            float s2 = ref_sigmoid(v.z), s3 = ref_sigmoid(v.w);
            if (s0 > best) { best = s0; bl = 4 * q + 0; }
            if (s1 > best) { best = s1; bl = 4 * q + 1; }
            if (s2 > best) { best = s2; bl = 4 * q + 2; }
            if (s3 > best) { best = s3; bl = 4 * q + 3; }
        }
        float4 rg = ((const float4*)reg)[i];
        float4 an = ((const float4*)anc)[i];
        float ox = fminf(fmaxf(rg.x * an.z, -32.0f), 32.0f);
        float oy = fminf(fmaxf(rg.y * an.w, -32.0f), 32.0f);
        float cx = an.x + ox, cy = an.y + oy;
        float w = an.z * expf(fminf(rg.z, SCALE_CLAMP));
        float h = an.w * expf(fminf(rg.w, SCALE_CLAMP));
        float x1 = fminf(fmaxf((cx - 0.5f * w) * IMG_INV, 0.0f), 1.0f);
        float y1 = fminf(fmaxf((cy - 0.5f * h) * IMG_INV, 0.0f), 1.0f);
        float x2 = fminf(fmaxf((cx + 0.5f * w) * IMG_INV, 0.0f), 1.0f);
        float y2 = fminf(fmaxf((cy + 0.5f * h) * IMG_INV, 0.0f), 1.0f);
        out[4 * t + 0] = x1; out[4 * t + 1] = y1;
        out[4 * t + 2] = x2; out[4 * t + 3] = y2;
        out[4000 + t] = best;
        out[5000 + t] = (float)bl;
        g_boxes[t] = make_float4(x1, y1, x2, y2);
        g_labels[t] = bl;
        g_valid[t] = (best >= 0.05f) ? 1 : 0;
    }
    gridsync(7);

    // ===== phase 8: suppression bitmask (warp per 32-wide word) =============
    {
        int lane = t & 31;
        int gw = b * (NTHR / 32) + (t >> 5);          // global warp id
        for (int task = gw; task < K_TOP * 32; task += GRID * (NTHR / 32)) {
            int i = task >> 5, W = task & 31;
            float4 bi = g_boxes[i];
            int li = g_labels[i];
            float ai = (bi.z - bi.x) * (bi.w - bi.y);
            int j = W * 32 + lane;
            bool sup = false;
            if (j < i && g_labels[j] == li) {
                float4 bj = g_boxes[j];
                float xx1 = fmaxf(bi.x, bj.x), yy1 = fmaxf(bi.y, bj.y);
                float xx2 = fminf(bi.z, bj.z), yy2 = fminf(bi.w, bj.w);
                float ww = fmaxf(1e-10f, xx2 - xx1);
                float hh = fmaxf(1e-10f, yy2 - yy1);
                float inter = ww * hh;
                float aj = (bj.z - bj.x) * (bj.w - bj.y);
                float iou = inter / (ai + aj - inter + 1e-10f);
                sup = iou > 0.6f;
            }
            unsigned bits = __ballot_sync(0xffffffffu, sup);
            if (lane == 0) g_mask[task] = bits;
        }
        if (b == GRID - 3 && t == 0) g_candCount = 0u;
    }
    gridsync(8);   // FINAL barrier: resets g_barrier to 0 for next run

    // ===== phase 9: block0 serial greedy NMS ================================
    if (b == 0) {
        unsigned* sm = smem_u;                 // [K_TOP*32]
        unsigned* smv = smem_u + K_TOP * 32;   // [K_TOP]
        const uint4* mp = (const uint4*)g_mask;
        uint4* sp = (uint4*)sm;
        for (int idx = t; idx < K_TOP * 8; idx += NTHR) sp[idx] = mp[idx];
        for (int idx = t; idx < K_TOP; idx += NTHR) smv[idx] = (unsigned)g_valid[idx];
        __syncthreads();
        if (t < 32) {
            unsigned keepw = 0u;
            unsigned cur = sm[t];
            unsigned vcur = smv[0];
            for (int i = 0; i < K_TOP; i++) {
                unsigned nxt  = (i < K_TOP - 1) ? sm[(i + 1) * 32 + t] : 0u;
                unsigned vnxt = (i < K_TOP - 1) ? smv[i + 1] : 0u;
                bool ov = __any_sync(0xffffffffu, (cur & keepw) != 0u);
                bool kp = (vcur != 0u) && !ov;
                if (kp && t == (i >> 5)) keepw |= (1u << (i & 31));
                cur = nxt; vcur = vnxt;
            }
#pragma unroll
            for (int bb = 0; bb < 32; bb++) {
                int i = t * 32 + bb;
                if (i < K_TOP) out[6000 + i] = ((keepw >> bb) & 1u) ? 1.0f : 0.0f;
            }
        }
    }
}

// ---------------- launcher ---------------------------------------------------
extern "C" void kernel_launch(void* const* d_in, const int* in_sizes, int n_in,
                              void* d_out, int out_size) {
    const float* cls = (const float*)d_in[0];
    const float* reg = (const float*)d_in[1];
    const float* anc = (const float*)d_in[2];
    float* out = (float*)d_out;
    (void)in_sizes; (void)n_in; (void)out_size;

    cudaFuncSetAttribute(k_mega, cudaFuncAttributeMaxDynamicSharedMemorySize,
                         SMEM_BYTES);
    k_mega<<<GRID, NTHR, SMEM_BYTES>>>(cls, reg, anc, out);
}

// round 5
// speedup vs baseline: 1.1549x; 1.1549x over previous
#include <cuda_runtime.h>
#include <math.h>

#define M_ANCH   589824
#define NCLS     80
#define K_TOP    1000
#define CAND_CAP 4096
#define NBINS    2048
#define GRID     576
#define NTHR     256
#define ROWS_PER_BLK 1024          /* M_ANCH / GRID */
#define NBAR_FINAL 7
#define IMG_INV  (1.0f/2048.0f)
#define SCALE_CLAMP 4.1351665567423560f   /* log(1000/16) */

// ---------------- scratch (device globals; no allocations allowed) ----------
__device__ unsigned            g_key[M_ANCH];
__device__ unsigned            g_hist1[NBINS];
__device__ unsigned            g_hist2[NBINS];
__device__ unsigned            g_B1;
__device__ unsigned            g_cntAbove1;
__device__ unsigned            g_thresh;
__device__ unsigned            g_candCount;
__device__ unsigned long long  g_cand[CAND_CAP];
__device__ int                 g_selIdx[K_TOP];
__device__ float4              g_boxes[K_TOP];
__device__ int                 g_labels[K_TOP];
__device__ int                 g_valid[K_TOP];
__device__ unsigned            g_mask[K_TOP * 32];
__device__ unsigned            g_barrier;   // starts 0; self-resets every run

// ---------------- helpers ---------------------------------------------------
__device__ __forceinline__ unsigned f2ord(float f) {
    unsigned u = __float_as_uint(f);
    return (u & 0x80000000u) ? ~u : (u | 0x80000000u);
}
// Sigmoid matching XLA lowering of lax.logistic on GPU (bit-stable vs ref).
__device__ __forceinline__ float ref_sigmoid(float x) {
    float e = expf(-x);
    return __fdiv_rn(1.0f, __fadd_rn(1.0f, e));
}

__device__ __forceinline__ void gridsync(int k) {
    __syncthreads();
    if (threadIdx.x == 0) {
        __threadfence();
        unsigned target = (unsigned)k * GRID;
        unsigned old = atomicAdd(&g_barrier, 1u);
        volatile unsigned* p = &g_barrier;
        if (k == NBAR_FINAL) {
            if (old + 1u == target) {
                atomicExch(&g_barrier, 0u);
            } else {
                while (true) { unsigned v = *p; if (v == 0u || v >= target) break; }
            }
        } else {
            while (*p < target) { }
        }
        __threadfence();
    }
    __syncthreads();
}

// 256-thread find: largest bin b with base_extra + suffix(b) >= K_TOP.
// Thread t owns bins [t*8, t*8+8). Also returns count strictly above b.
__device__ void find_thresh(const unsigned* __restrict__ gh, unsigned base_extra,
                            unsigned* out_bin, unsigned* out_above) {
    __shared__ unsigned ssum[NTHR];
    __shared__ unsigned long long sbest;
    int t = threadIdx.x;
    unsigned h[8];
    unsigned s = 0;
#pragma unroll
    for (int e = 0; e < 8; e++) { h[e] = gh[t * 8 + e]; s += h[e]; }
    ssum[t] = s;
    if (t == 0) sbest = 0ULL;
    __syncthreads();
    for (int off = 1; off < NTHR; off <<= 1) {
        unsigned a = (t + off < NTHR) ? ssum[t + off] : 0u;
        __syncthreads();
        ssum[t] += a;
        __syncthreads();
    }
    unsigned run = ssum[t] - s;          // exclusive suffix of later threads
    unsigned long long cand = 0ULL;
#pragma unroll
    for (int e = 7; e >= 0; e--) {
        run += h[e];
        if (base_extra + run >= K_TOP) {
            cand = ((unsigned long long)(t * 8 + e) << 32) | run;
            break;                        // highest qualifying bin in this thread
        }
    }
    if (cand) atomicMax(&sbest, cand);
    __syncthreads();
    if (t == 0) {
        unsigned bin = (unsigned)(sbest >> 32);
        *out_bin = bin;
        if (out_above) *out_above = (unsigned)(sbest & 0xFFFFFFFFu) - gh[bin];
    }
    __syncthreads();
}

// ---------------- the mega kernel (phases 1-8) ------------------------------
__global__ void __launch_bounds__(NTHR, 4)
k_mega(const float* __restrict__ cls, const float* __restrict__ reg,
       const float* __restrict__ anc, float* __restrict__ out) {
    __shared__ unsigned sh[NBINS];
    const int t = threadIdx.x;
    const int b = blockIdx.x;
    const int warpId = t >> 5;
    const int lane = t & 31;

    // ===== phase 1: rowmax (4 lanes/row, line-aligned 64B windows) + hist1 ===
    {
#pragma unroll
        for (int e = t; e < NBINS; e += NTHR) sh[e] = 0u;
        __syncthreads();
        const int g = lane >> 2;          // group 0..7 -> row within pass
        const int gl = lane & 3;          // lane within group
        const int blockRowBase = b * ROWS_PER_BLK;
#pragma unroll 2
        for (int p = 0; p < 16; p++) {
            int row = blockRowBase + p * 64 + warpId * 8 + g;
            const float* rp = cls + (size_t)row * NCLS + gl * 4;
            float4 v0 = *(const float4*)(rp);
            float4 v1 = *(const float4*)(rp + 16);
            float4 v2 = *(const float4*)(rp + 32);
            float4 v3 = *(const float4*)(rp + 48);
            float4 v4 = *(const float4*)(rp + 64);
            float m = fmaxf(fmaxf(v0.x, v0.y), fmaxf(v0.z, v0.w));
            m = fmaxf(m, fmaxf(fmaxf(v1.x, v1.y), fmaxf(v1.z, v1.w)));
            m = fmaxf(m, fmaxf(fmaxf(v2.x, v2.y), fmaxf(v2.z, v2.w)));
            m = fmaxf(m, fmaxf(fmaxf(v3.x, v3.y), fmaxf(v3.z, v3.w)));
            m = fmaxf(m, fmaxf(fmaxf(v4.x, v4.y), fmaxf(v4.z, v4.w)));
            m = fmaxf(m, __shfl_xor_sync(0xffffffffu, m, 1));
            m = fmaxf(m, __shfl_xor_sync(0xffffffffu, m, 2));
            if (gl == 0) {
                unsigned key = f2ord(ref_sigmoid(m));
                g_key[row] = key;
                atomicAdd(&sh[key >> 21], 1u);
            }
        }
        __syncthreads();
#pragma unroll
        for (int e = t; e < NBINS; e += NTHR) {
            unsigned c = sh[e];
            if (c) atomicAdd(&g_hist1[e], c);
        }
    }
    gridsync(1);

    // ===== phase 2: block0 finds coarse bin B1, zeroes hist1 ================
    if (b == 0) {
        unsigned bin, above;
        find_thresh(g_hist1, 0u, &bin, &above);
        if (t == 0) { g_B1 = bin; g_cntAbove1 = above; }
        for (int e = t; e < NBINS; e += NTHR) g_hist1[e] = 0u;
    }
    gridsync(2);

    // ===== phase 3: refined histogram within bin B1 =========================
    {
        for (int e = t; e < NBINS; e += NTHR) sh[e] = 0u;
        __syncthreads();
        unsigned B1 = g_B1;
        const uint4* kp = (const uint4*)g_key;
        uint4 k4 = kp[b * NTHR + t];
        if ((k4.x >> 21) == B1) atomicAdd(&sh[(k4.x >> 10) & 2047u], 1u);
        if ((k4.y >> 21) == B1) atomicAdd(&sh[(k4.y >> 10) & 2047u], 1u);
        if ((k4.z >> 21) == B1) atomicAdd(&sh[(k4.z >> 10) & 2047u], 1u);
        if ((k4.w >> 21) == B1) atomicAdd(&sh[(k4.w >> 10) & 2047u], 1u);
        __syncthreads();
        for (int e = t; e < NBINS; e += NTHR) {
            unsigned c = sh[e];
            if (c) atomicAdd(&g_hist2[e], c);
        }
    }
    gridsync(3);

    // ===== phase 4: block0 finds refined threshold, zeroes hist2 ============
    if (b == 0) {
        unsigned bin2;
        find_thresh(g_hist2, g_cntAbove1, &bin2, 0);
        if (t == 0) g_thresh = (g_B1 << 21) | (bin2 << 10);
        for (int e = t; e < NBINS; e += NTHR) g_hist2[e] = 0u;
    }
    gridsync(4);

    // ===== phase 5: compact (warp-aggregated atomics) =======================
    {
        unsigned thr = g_thresh;
        const uint4* kp = (const uint4*)g_key;
        int i4 = b * NTHR + t;
        uint4 k4 = kp[i4];
        int i0 = i4 * 4;
        unsigned keys[4] = { k4.x, k4.y, k4.z, k4.w };
#pragma unroll
        for (int c = 0; c < 4; c++) {
            bool f = keys[c] >= thr;
            unsigned bal = __ballot_sync(0xffffffffu, f);
            if (bal) {
                unsigned base;
                if (lane == 0) base = atomicAdd(&g_candCount, (unsigned)__popc(bal));
                base = __shfl_sync(0xffffffffu, base, 0);
                if (f) {
                    unsigned pos = base + __popc(bal & ((1u << lane) - 1u));
                    if (pos < CAND_CAP)
                        g_cand[pos] = ((unsigned long long)keys[c] << 32) |
                                      (unsigned)(~(i0 + c));
                }
            }
        }
    }
    gridsync(5);

    // ===== phase 6: O(n^2) rank (L1-broadcast scan of g_cand) ===============
    {
        unsigned cnt = min(g_candCount, (unsigned)CAND_CAP);
        unsigned id = b * NTHR + t;
        if ((unsigned)(b * NTHR) < cnt) {
            unsigned long long my = (id < cnt) ? g_cand[id] : 0ULL;
            unsigned rank = 0, j = 0;
            for (; j + 4 <= cnt; j += 4) {
                unsigned long long a0 = g_cand[j],     a1 = g_cand[j + 1];
                unsigned long long a2 = g_cand[j + 2], a3 = g_cand[j + 3];
                rank += (a0 > my) + (a1 > my) + (a2 > my) + (a3 > my);
            }
            for (; j < cnt; j++) rank += (g_cand[j] > my);
            if (id < cnt && rank < K_TOP)
                g_selIdx[rank] = (int)(~(unsigned)(my & 0xFFFFFFFFULL));
        }
    }
    gridsync(6);

    // ===== phase 7: decode 1000 winners (blocks 0-3); blk4 resets counter ===
    if (b < 4) {
        int j = b * NTHR + t;
        if (j < K_TOP) {
            int i = g_selIdx[j];
            const float4* row = (const float4*)(cls + (size_t)i * NCLS);
            float best = -1.0f; int bl = 0;
#pragma unroll
            for (int q = 0; q < NCLS / 4; q++) {
                float4 v = row[q];
                float s0 = ref_sigmoid(v.x), s1 = ref_sigmoid(v.y);
                float s2 = ref_sigmoid(v.z), s3 = ref_sigmoid(v.w);
                if (s0 > best) { best = s0; bl = 4 * q + 0; }
                if (s1 > best) { best = s1; bl = 4 * q + 1; }
                if (s2 > best) { best = s2; bl = 4 * q + 2; }
                if (s3 > best) { best = s3; bl = 4 * q + 3; }
            }
            float4 rg = ((const float4*)reg)[i];
            float4 an = ((const float4*)anc)[i];
            float ox = fminf(fmaxf(rg.x * an.z, -32.0f), 32.0f);
            float oy = fminf(fmaxf(rg.y * an.w, -32.0f), 32.0f);
            float cx = an.x + ox, cy = an.y + oy;
            float w = an.z * expf(fminf(rg.z, SCALE_CLAMP));
            float h = an.w * expf(fminf(rg.w, SCALE_CLAMP));
            float x1 = fminf(fmaxf((cx - 0.5f * w) * IMG_INV, 0.0f), 1.0f);
            float y1 = fminf(fmaxf((cy - 0.5f * h) * IMG_INV, 0.0f), 1.0f);
            float x2 = fminf(fmaxf((cx + 0.5f * w) * IMG_INV, 0.0f), 1.0f);
            float y2 = fminf(fmaxf((cy + 0.5f * h) * IMG_INV, 0.0f), 1.0f);
            out[4 * j + 0] = x1; out[4 * j + 1] = y1;
            out[4 * j + 2] = x2; out[4 * j + 3] = y2;
            out[4000 + j] = best;
            out[5000 + j] = (float)bl;
            g_boxes[j] = make_float4(x1, y1, x2, y2);
            g_labels[j] = bl;
            g_valid[j] = (best >= 0.05f) ? 1 : 0;
        }
    }
    if (b == 4 && t == 0) g_candCount = 0u;
    gridsync(7);   // FINAL barrier in this kernel: resets g_barrier

    // ===== phase 8: suppression bitmask (warp per 32-candidate word) ========
    {
        int gw = b * (NTHR / 32) + warpId;
        for (int task = gw; task < K_TOP * 32; task += GRID * (NTHR / 32)) {
            int i = task >> 5, W = task & 31;
            float4 bi = g_boxes[i];
            int li = g_labels[i];
            float ai = (bi.z - bi.x) * (bi.w - bi.y);
            int j = W * 32 + lane;
            bool sup = false;
            if (j < i && g_labels[j] == li) {
                float4 bj = g_boxes[j];
                float xx1 = fmaxf(bi.x, bj.x), yy1 = fmaxf(bi.y, bj.y);
                float xx2 = fminf(bi.z, bj.z), yy2 = fminf(bi.w, bj.w);
                float ww = fmaxf(1e-10f, xx2 - xx1);
                float hh = fmaxf(1e-10f, yy2 - yy1);
                float inter = ww * hh;
                float aj = (bj.z - bj.x) * (bj.w - bj.y);
                float iou = inter / (ai + aj - inter + 1e-10f);
                sup = iou > 0.6f;
            }
            unsigned bits = __ballot_sync(0xffffffffu, sup);
            if (lane == 0) g_mask[task] = bits;
        }
    }
}

// serial greedy NMS: 1 block; mask + valid staged in 132KB smem; warp 0 loop
__global__ void k_nms(float* __restrict__ out) {
    extern __shared__ unsigned sm[];          // [K_TOP*32] mask + [K_TOP] valid
    unsigned* smv = sm + K_TOP * 32;
    const uint4* mp = (const uint4*)g_mask;
    uint4* sp = (uint4*)sm;
    for (int idx = threadIdx.x; idx < K_TOP * 8; idx += blockDim.x)
        sp[idx] = mp[idx];
    for (int idx = threadIdx.x; idx < K_TOP; idx += blockDim.x)
        smv[idx] = (unsigned)g_valid[idx];
    __syncthreads();
    if (threadIdx.x >= 32) return;
    int t = threadIdx.x;

    unsigned keepw = 0u;
    unsigned cur = sm[t];
    unsigned vcur = smv[0];
    for (int i = 0; i < K_TOP; i++) {
        unsigned nxt  = (i < K_TOP - 1) ? sm[(i + 1) * 32 + t] : 0u;
        unsigned vnxt = (i < K_TOP - 1) ? smv[i + 1] : 0u;
        bool ov = __any_sync(0xffffffffu, (cur & keepw) != 0u);
        bool kp = (vcur != 0u) && !ov;
        if (kp && t == (i >> 5)) keepw |= (1u << (i & 31));
        cur = nxt; vcur = vnxt;
    }
#pragma unroll
    for (int bb = 0; bb < 32; bb++) {
        int i = t * 32 + bb;
        if (i < K_TOP) out[6000 + i] = ((keepw >> bb) & 1u) ? 1.0f : 0.0f;
    }
}

// ---------------- launcher ---------------------------------------------------
extern "C" void kernel_launch(void* const* d_in, const int* in_sizes, int n_in,
                              void* d_out, int out_size) {
    const float* cls = (const float*)d_in[0];
    const float* reg = (const float*)d_in[1];
    const float* anc = (const float*)d_in[2];
    float* out = (float*)d_out;
    (void)in_sizes; (void)n_in; (void)out_size;

    cudaFuncSetAttribute(k_nms, cudaFuncAttributeMaxDynamicSharedMemorySize,
                         (K_TOP * 32 + K_TOP) * (int)sizeof(unsigned));

    k_mega<<<GRID, NTHR>>>(cls, reg, anc, out);
    k_nms<<<1, 1024, (K_TOP * 32 + K_TOP) * sizeof(unsigned)>>>(out);
}

// round 6
// speedup vs baseline: 1.4009x; 1.2130x over previous
#include <cuda_runtime.h>
#include <math.h>

#define M_ANCH   589824
#define NCLS     80
#define K_TOP    1000
#define CAND_CAP 4096
#define NBINS    2048
#define GRID     576
#define NTHR     256
#define ROWS_PER_BLK 1024          /* M_ANCH / GRID */
#define NBAR_FINAL 5
#define IMG_INV  (1.0f/2048.0f)
#define SCALE_CLAMP 4.1351665567423560f   /* log(1000/16) */

// ---------------- scratch (device globals; no allocations allowed) ----------
__device__ unsigned            g_key[M_ANCH];
__device__ unsigned            g_hist1[NBINS];
__device__ unsigned            g_hist2[NBINS];
__device__ unsigned            g_candCount;
__device__ unsigned long long  g_cand[CAND_CAP];
__device__ float4              g_boxes[K_TOP];
__device__ int                 g_labels[K_TOP];
__device__ unsigned            g_validw[32];     // 1000-bit valid bitset
__device__ unsigned            g_colnz[32];      // 1000-bit "column nonzero"
__device__ unsigned            g_mask[K_TOP * 32];
__device__ unsigned            g_barrier;        // starts 0; self-resets

// ---------------- helpers ---------------------------------------------------
__device__ __forceinline__ unsigned f2ord(float f) {
    unsigned u = __float_as_uint(f);
    return (u & 0x80000000u) ? ~u : (u | 0x80000000u);
}
// Sigmoid matching XLA lowering of lax.logistic on GPU (bit-stable vs ref).
__device__ __forceinline__ float ref_sigmoid(float x) {
    float e = expf(-x);
    return __fdiv_rn(1.0f, __fadd_rn(1.0f, e));
}

__device__ __forceinline__ void gridsync(int k) {
    __syncthreads();
    if (threadIdx.x == 0) {
        __threadfence();
        unsigned target = (unsigned)k * GRID;
        unsigned old = atomicAdd(&g_barrier, 1u);
        volatile unsigned* p = &g_barrier;
        if (k == NBAR_FINAL) {
            if (old + 1u == target) {
                atomicExch(&g_barrier, 0u);
            } else {
                while (true) { unsigned v = *p; if (v == 0u || v >= target) break; }
            }
        } else {
            while (*p < target) { }
        }
        __threadfence();
    }
    __syncthreads();
}

// 256-thread find over a 2048-bin global hist: largest bin with
// base_extra + suffix(bin) >= K_TOP. Results in shared vars (all threads see).
__device__ void find_thresh(const unsigned* __restrict__ gh, unsigned base_extra,
                            unsigned* s_bin, unsigned* s_above) {
    __shared__ unsigned ssum[NTHR];
    __shared__ unsigned long long sbest;
    int t = threadIdx.x;
    unsigned h[8];
    unsigned s = 0;
#pragma unroll
    for (int e = 0; e < 8; e++) { h[e] = gh[t * 8 + e]; s += h[e]; }
    ssum[t] = s;
    if (t == 0) sbest = 0ULL;
    __syncthreads();
    for (int off = 1; off < NTHR; off <<= 1) {
        unsigned a = (t + off < NTHR) ? ssum[t + off] : 0u;
        __syncthreads();
        ssum[t] += a;
        __syncthreads();
    }
    unsigned run = ssum[t] - s;
    unsigned long long cand = 0ULL;
#pragma unroll
    for (int e = 7; e >= 0; e--) {
        run += h[e];
        if (base_extra + run >= K_TOP) {
            cand = ((unsigned long long)(t * 8 + e) << 32) | run;
            break;
        }
    }
    if (cand) atomicMax(&sbest, cand);
    __syncthreads();
    if (t == 0) {
        unsigned bin = (unsigned)(sbest >> 32);
        *s_bin = bin;
        if (s_above) *s_above = (unsigned)(sbest & 0xFFFFFFFFu) - gh[bin];
    }
    __syncthreads();
}

// ---------------- the single mega kernel -------------------------------------
__global__ void __launch_bounds__(NTHR, 4)
k_mega(const float* __restrict__ cls, const float* __restrict__ reg,
       const float* __restrict__ anc, float* __restrict__ out) {
    __shared__ unsigned sh[NBINS];
    __shared__ unsigned sB1, sAbove, sBin2;
    const int t = threadIdx.x;
    const int b = blockIdx.x;
    const int warpId = t >> 5;
    const int lane = t & 31;

    // ===== P1: rowmax (4 lanes/row, 64B-aligned windows) + hist1 ============
    {
        for (int e = t; e < NBINS; e += NTHR) sh[e] = 0u;
        __syncthreads();
        const int g = lane >> 2;
        const int gl = lane & 3;
        const int blockRowBase = b * ROWS_PER_BLK;
#pragma unroll 2
        for (int p = 0; p < 16; p++) {
            int row = blockRowBase + p * 64 + warpId * 8 + g;
            const float* rp = cls + (size_t)row * NCLS + gl * 4;
            float4 v0 = *(const float4*)(rp);
            float4 v1 = *(const float4*)(rp + 16);
            float4 v2 = *(const float4*)(rp + 32);
            float4 v3 = *(const float4*)(rp + 48);
            float4 v4 = *(const float4*)(rp + 64);
            float m = fmaxf(fmaxf(v0.x, v0.y), fmaxf(v0.z, v0.w));
            m = fmaxf(m, fmaxf(fmaxf(v1.x, v1.y), fmaxf(v1.z, v1.w)));
            m = fmaxf(m, fmaxf(fmaxf(v2.x, v2.y), fmaxf(v2.z, v2.w)));
            m = fmaxf(m, fmaxf(fmaxf(v3.x, v3.y), fmaxf(v3.z, v3.w)));
            m = fmaxf(m, fmaxf(fmaxf(v4.x, v4.y), fmaxf(v4.z, v4.w)));
            m = fmaxf(m, __shfl_xor_sync(0xffffffffu, m, 1));
            m = fmaxf(m, __shfl_xor_sync(0xffffffffu, m, 2));
            if (gl == 0) {
                unsigned key = f2ord(ref_sigmoid(m));
                g_key[row] = key;
                atomicAdd(&sh[key >> 21], 1u);
            }
        }
        // zero the small bitsets for this run (writers run in P4/P5)
        if (b == 400 && t < 32) { g_validw[t] = 0u; g_colnz[t] = 0u; }
        __syncthreads();
        for (int e = t; e < NBINS; e += NTHR) {
            unsigned c = sh[e];
            if (c) atomicAdd(&g_hist1[e], c);
        }
    }
    gridsync(1);

    // ===== P2: all blocks find B1 redundantly; hist2 of bin B1 ==============
    unsigned B1, above;
    {
        find_thresh(g_hist1, 0u, &sB1, &sAbove);
        B1 = sB1; above = sAbove;
        for (int e = t; e < NBINS; e += NTHR) sh[e] = 0u;
        __syncthreads();
        const uint4* kp = (const uint4*)g_key;
        uint4 k4 = kp[b * NTHR + t];
        if ((k4.x >> 21) == B1) atomicAdd(&sh[(k4.x >> 10) & 2047u], 1u);
        if ((k4.y >> 21) == B1) atomicAdd(&sh[(k4.y >> 10) & 2047u], 1u);
        if ((k4.z >> 21) == B1) atomicAdd(&sh[(k4.z >> 10) & 2047u], 1u);
        if ((k4.w >> 21) == B1) atomicAdd(&sh[(k4.w >> 10) & 2047u], 1u);
        __syncthreads();
        for (int e = t; e < NBINS; e += NTHR) {
            unsigned c = sh[e];
            if (c) atomicAdd(&g_hist2[e], c);
        }
    }
    gridsync(2);

    // ===== P3: all blocks find refined threshold; compact ===================
    {
        find_thresh(g_hist2, above, &sBin2, 0);
        unsigned thr = (B1 << 21) | (sBin2 << 10);
        const uint4* kp = (const uint4*)g_key;
        int i4 = b * NTHR + t;
        uint4 k4 = kp[i4];
        int i0 = i4 * 4;
        unsigned keys[4] = { k4.x, k4.y, k4.z, k4.w };
#pragma unroll
        for (int c = 0; c < 4; c++) {
            bool f = keys[c] >= thr;
            unsigned bal = __ballot_sync(0xffffffffu, f);
            if (bal) {
                unsigned base;
                if (lane == 0) base = atomicAdd(&g_candCount, (unsigned)__popc(bal));
                base = __shfl_sync(0xffffffffu, base, 0);
                if (f) {
                    unsigned pos = base + __popc(bal & ((1u << lane) - 1u));
                    if (pos < CAND_CAP)
                        g_cand[pos] = ((unsigned long long)keys[c] << 32) |
                                      (unsigned)(~(i0 + c));
                }
            }
        }
    }
    gridsync(3);

    // ===== P4: rank + decode fused; idle blocks zero the histograms =========
    {
        unsigned cnt = min(g_candCount, (unsigned)CAND_CAP);
        unsigned id = b * NTHR + t;
        if ((unsigned)(b * NTHR) < cnt) {
            unsigned long long my = (id < cnt) ? g_cand[id] : 0ULL;
            unsigned rank = 0, jj = 0;
            for (; jj + 4 <= cnt; jj += 4) {
                unsigned long long a0 = g_cand[jj],     a1 = g_cand[jj + 1];
                unsigned long long a2 = g_cand[jj + 2], a3 = g_cand[jj + 3];
                rank += (a0 > my) + (a1 > my) + (a2 > my) + (a3 > my);
            }
            for (; jj < cnt; jj++) rank += (g_cand[jj] > my);
            if (id < cnt && rank < K_TOP) {
                int i = (int)(~(unsigned)(my & 0xFFFFFFFFULL));
                int j = (int)rank;
                const float4* row = (const float4*)(cls + (size_t)i * NCLS);
                float best = -1.0f; int bl = 0;
#pragma unroll
                for (int q = 0; q < NCLS / 4; q++) {
                    float4 v = row[q];
                    float s0 = ref_sigmoid(v.x), s1 = ref_sigmoid(v.y);
                    float s2 = ref_sigmoid(v.z), s3 = ref_sigmoid(v.w);
                    if (s0 > best) { best = s0; bl = 4 * q + 0; }
                    if (s1 > best) { best = s1; bl = 4 * q + 1; }
                    if (s2 > best) { best = s2; bl = 4 * q + 2; }
                    if (s3 > best) { best = s3; bl = 4 * q + 3; }
                }
                float4 rg = ((const float4*)reg)[i];
                float4 an = ((const float4*)anc)[i];
                float ox = fminf(fmaxf(rg.x * an.z, -32.0f), 32.0f);
                float oy = fminf(fmaxf(rg.y * an.w, -32.0f), 32.0f);
                float cx = an.x + ox, cy = an.y + oy;
                float w = an.z * expf(fminf(rg.z, SCALE_CLAMP));
                float h = an.w * expf(fminf(rg.w, SCALE_CLAMP));
                float x1 = fminf(fmaxf((cx - 0.5f * w) * IMG_INV, 0.0f), 1.0f);
                float y1 = fminf(fmaxf((cy - 0.5f * h) * IMG_INV, 0.0f), 1.0f);
                float x2 = fminf(fmaxf((cx + 0.5f * w) * IMG_INV, 0.0f), 1.0f);
                float y2 = fminf(fmaxf((cy + 0.5f * h) * IMG_INV, 0.0f), 1.0f);
                out[4 * j + 0] = x1; out[4 * j + 1] = y1;
                out[4 * j + 2] = x2; out[4 * j + 3] = y2;
                out[4000 + j] = best;
                out[5000 + j] = (float)bl;
                g_boxes[j] = make_float4(x1, y1, x2, y2);
                g_labels[j] = bl;
                if (best >= 0.05f)
                    atomicOr(&g_validw[j >> 5], 1u << (j & 31));
            }
        }
        // cleanup for next run: hist1 by blocks 560-567, hist2 by 568-575
        if (b >= 560 && b < 568) g_hist1[(b - 560) * NTHR + t] = 0u;
        if (b >= 568 && b < 576) g_hist2[(b - 568) * NTHR + t] = 0u;
    }
    gridsync(4);

    // ===== P5: suppression bitmask + column-nonzero bitset ==================
    {
        int gw = b * (NTHR / 32) + warpId;
        for (int task = gw; task < K_TOP * 32; task += GRID * (NTHR / 32)) {
            int i = task >> 5, W = task & 31;
            float4 bi = g_boxes[i];
            int li = g_labels[i];
            float ai = (bi.z - bi.x) * (bi.w - bi.y);
            int j = W * 32 + lane;
            bool sup = false;
            if (j < i && g_labels[j] == li) {
                float4 bj = g_boxes[j];
                float xx1 = fmaxf(bi.x, bj.x), yy1 = fmaxf(bi.y, bj.y);
                float xx2 = fminf(bi.z, bj.z), yy2 = fminf(bi.w, bj.w);
                float ww = fmaxf(1e-10f, xx2 - xx1);
                float hh = fmaxf(1e-10f, yy2 - yy1);
                float inter = ww * hh;
                float aj = (bj.z - bj.x) * (bj.w - bj.y);
                float iou = inter / (ai + aj - inter + 1e-10f);
                sup = iou > 0.6f;
            }
            unsigned bits = __ballot_sync(0xffffffffu, sup);
            if (lane == 0) {
                g_mask[task] = bits;
                if (bits) atomicOr(&g_colnz[i >> 5], 1u << (i & 31));
            }
        }
        if (b == 5 && t == 0) g_candCount = 0u;
    }
    gridsync(5);   // FINAL: self-resets g_barrier

    // ===== P6: block0 sparse greedy NMS =====================================
    if (b == 0 && t < 32) {
        unsigned vw = g_validw[t];
        unsigned cz = g_colnz[t];
        unsigned kw = vw & ~cz;            // zero-column candidates: keep=valid
        for (int w = 0; w < 32; w++) {
            unsigned word  = __shfl_sync(0xffffffffu, cz, w);
            unsigned vword = __shfl_sync(0xffffffffu, vw, w);
            while (word) {
                int bbit = __ffs(word) - 1;
                word &= word - 1u;
                int i = w * 32 + bbit;
                unsigned colw = g_mask[i * 32 + t];
                bool ov = __any_sync(0xffffffffu, (colw & kw) != 0u);
                bool kp = ((vword >> bbit) & 1u) && !ov;
                if (kp && t == w) kw |= (1u << bbit);
            }
        }
#pragma unroll
        for (int e = 0; e < 32; e++) {
            int i = t * 32 + e;
            if (i < K_TOP) out[6000 + i] = ((kw >> e) & 1u) ? 1.0f : 0.0f;
        }
    }
}

// ---------------- launcher ---------------------------------------------------
extern "C" void kernel_launch(void* const* d_in, const int* in_sizes, int n_in,
                              void* d_out, int out_size) {
    const float* cls = (const float*)d_in[0];
    const float* reg = (const float*)d_in[1];
    const float* anc = (const float*)d_in[2];
    float* out = (float*)d_out;
    (void)in_sizes; (void)n_in; (void)out_size;

    k_mega<<<GRID, NTHR>>>(cls, reg, anc, out);
}